// round 12
// baseline (speedup 1.0000x reference)
#include <cuda_runtime.h>
#include <cuda_fp16.h>
#include <cstdint>

static constexpr int M_TOT = 8192;   // B * S
static constexpr int N_TOT = 4096;   // D_OUT
static constexpr int K_TOT = 4096;   // D_IN

static constexpr int BM = 128;
static constexpr int BN = 256;
static constexpr int BK = 128;                     // two 64-col sub-blocks
static constexpr int SUBK = 64;
static constexpr int STAGES = 2;
static constexpr int KITERS = K_TOT / BK;          // 32
static constexpr int ROW_BYTES = SUBK * 2;         // 128 B rows (SW128 atom)
static constexpr int A_SUB = BM * ROW_BYTES;       // 16384
static constexpr int A_BYTES = 2 * A_SUB;          // 32768
static constexpr int B_SUB = BN * ROW_BYTES;       // 32768
static constexpr int B_BYTES = 2 * B_SUB;          // 65536
static constexpr int STAGE_BYTES = A_BYTES + B_BYTES;  // 98304

static constexpr int NTHREADS = 256;               // 8 warps, 64x64 warp tiles

static constexpr int OFF_FULL  = 0;                // 2 mbarriers (8B)
static constexpr int OFF_EMPTY = 64;               // 2 mbarriers (8B)
static constexpr int OFF_SCALE = 1024;             // 256 f32
static constexpr int OFF_BIAS  = 2048;             // 256 f32
static constexpr int OFF_TILES = 3072;
static constexpr int SMEM_TOTAL = OFF_TILES + STAGES * STAGE_BYTES;  // 199680

// Scratch fp16 operands (allocation-free rule: __device__ globals)
__device__ __align__(16) __half g_xh[(size_t)M_TOT * K_TOT];   // 64 MiB
__device__ __align__(16) __half g_wh[(size_t)N_TOT * K_TOT];   // 32 MiB

// ---------------------------------------------------------------------------
// helpers
// ---------------------------------------------------------------------------
__device__ __forceinline__ uint32_t smem_u32(const void* p) {
    uint32_t a;
    asm("{ .reg .u64 t; cvta.to.shared.u64 t, %1; cvt.u32.u64 %0, t; }" : "=r"(a) : "l"(p));
    return a;
}
__device__ __forceinline__ uint32_t swz(uint32_t byte_off) {
    return byte_off ^ ((byte_off >> 3) & 0x70);
}
__device__ __forceinline__ void cp_async16(uint32_t saddr, const void* gptr) {
    asm volatile("cp.async.cg.shared.global [%0], [%1], 16;" :: "r"(saddr), "l"(gptr));
}
// arrive on mbar when ALL prior cp.async of this thread have completed
__device__ __forceinline__ void cp_async_mbar_arrive(uint32_t mbar) {
    asm volatile("cp.async.mbarrier.arrive.noinc.shared.b64 [%0];" :: "r"(mbar) : "memory");
}
#define MBARRIER_INIT(a, c) \
    asm volatile("mbarrier.init.shared.b64 [%0], %1;" :: "r"(a), "r"(c) : "memory")
#define MBARRIER_ARRIVE(a) \
    asm volatile("mbarrier.arrive.release.cta.shared::cta.b64 _, [%0];" :: "r"(a) : "memory")
#define MBARRIER_WAIT(a, ph) do {                                              \
    asm volatile("{\n\t.reg .pred P;\n\tWL_%=:\n\t"                            \
        "mbarrier.try_wait.parity.acquire.cta.shared::cta.b64 P, [%0], %1, 0x989680;\n\t" \
        "@P bra.uni WD_%=;\n\tbra.uni WL_%=;\n\tWD_%=:\n\t}"                   \
        :: "r"(a), "r"(ph) : "memory");                                        \
} while (0)

__device__ __forceinline__ void ldsm_x4(uint32_t& r0, uint32_t& r1,
                                        uint32_t& r2, uint32_t& r3, uint32_t addr) {
    asm volatile("ldmatrix.sync.aligned.m8n8.x4.shared.b16 {%0,%1,%2,%3}, [%4];"
                 : "=r"(r0), "=r"(r1), "=r"(r2), "=r"(r3) : "r"(addr));
}
__device__ __forceinline__ void mma16816(float& c0, float& c1, float& c2, float& c3,
                                         uint32_t a0, uint32_t a1, uint32_t a2, uint32_t a3,
                                         uint32_t b0, uint32_t b1) {
    asm volatile(
        "mma.sync.aligned.m16n8k16.row.col.f32.f16.f16.f32 "
        "{%0,%1,%2,%3}, {%4,%5,%6,%7}, {%8,%9}, {%0,%1,%2,%3};"
        : "+f"(c0), "+f"(c1), "+f"(c2), "+f"(c3)
        : "r"(a0), "r"(a1), "r"(a2), "r"(a3), "r"(b0), "r"(b1));
}

// ---------------------------------------------------------------------------
// fused conversion kernel: fp32->fp16 (x) and int32->fp16 (w) in one launch
// ---------------------------------------------------------------------------
static constexpr int N4X = (M_TOT * K_TOT) / 4;    // 8388608
static constexpr int N4W = (N_TOT * K_TOT) / 4;    // 4194304

__global__ void convert_all_kernel(const float* __restrict__ x,
                                   const int* __restrict__ w) {
    int i = blockIdx.x * blockDim.x + threadIdx.x;
    if (i < N4X) {
        float4 v = reinterpret_cast<const float4*>(x)[i];
        __half2* dst = reinterpret_cast<__half2*>(g_xh);
        dst[2 * i]     = __floats2half2_rn(v.x, v.y);
        dst[2 * i + 1] = __floats2half2_rn(v.z, v.w);
    } else {
        int j = i - N4X;
        if (j < N4W) {
            int4 v = reinterpret_cast<const int4*>(w)[j];
            __half2* dst = reinterpret_cast<__half2*>(g_wh);
            dst[2 * j]     = __halves2half2(__int2half_rn(v.x), __int2half_rn(v.y));
            dst[2 * j + 1] = __halves2half2(__int2half_rn(v.z), __int2half_rn(v.w));
        }
    }
}

// ---------------------------------------------------------------------------
// stage loader: 6144 x 16B cp.async (A: 2048, B: 4096 chunks), SW128 per sub
// ---------------------------------------------------------------------------
__device__ __forceinline__ void load_stage(int tid, uint32_t stage_base,
                                           int bm, int bn, int k0) {
#pragma unroll
    for (int i = 0; i < 24; i++) {
        int idx = tid + i * NTHREADS;
        if (idx < 2048) {                     // A: row(7b) | sub(1b) | c16(3b)
            int r   = idx >> 4;
            int s   = (idx >> 3) & 1;
            int c16 = idx & 7;
            uint32_t sw = swz((uint32_t)(r * ROW_BYTES + c16 * 16));
            cp_async16(stage_base + s * A_SUB + sw,
                       g_xh + (size_t)(bm + r) * K_TOT + k0 + s * SUBK + c16 * 8);
        } else {                              // B
            int j   = idx - 2048;
            int r   = j >> 4;
            int s   = (j >> 3) & 1;
            int c16 = j & 7;
            uint32_t sw = swz((uint32_t)(r * ROW_BYTES + c16 * 16));
            cp_async16(stage_base + A_BYTES + s * B_SUB + sw,
                       g_wh + (size_t)(bn + r) * K_TOT + k0 + s * SUBK + c16 * 8);
        }
    }
}

// ---------------------------------------------------------------------------
// GEMM: 128x256 block tile, BK=128 (2 sub-blocks), 2-stage mbarrier
//       producer/consumer — no __syncthreads in the mainloop, and only
//       32 iterations' worth of wait/arrive events (half of R10).
// ---------------------------------------------------------------------------
__global__ __launch_bounds__(NTHREADS, 1)
void qgemm_mma_kernel(const float* __restrict__ scale,
                      const float* __restrict__ bias,
                      float* __restrict__ out) {
    extern __shared__ __align__(1024) char smem[];
    const uint32_t sbase = smem_u32(smem);
    const int tid = threadIdx.x;
    const int wid = tid >> 5;
    const int l = tid & 31;

    const int bm = blockIdx.y * BM;
    const int bn = blockIdx.x * BN;
    const int wm = (wid & 1) * 64;     // warp M offset (0 or 64)
    const int wn = (wid >> 1) * 64;    // warp N offset (0,64,128,192)

    // init mbarriers (one thread), then converge once
    if (tid == 0) {
#pragma unroll
        for (int s = 0; s < STAGES; s++) {
            MBARRIER_INIT(sbase + OFF_FULL + 8 * s, NTHREADS);
            MBARRIER_INIT(sbase + OFF_EMPTY + 8 * s, NTHREADS);
        }
    }
    // scale/bias for this N tile into smem (read after pre-epilogue sync)
    reinterpret_cast<float*>(smem + OFF_SCALE)[tid] = scale[bn + tid];
    reinterpret_cast<float*>(smem + OFF_BIAS)[tid]  = bias[bn + tid];
    __syncthreads();

    float acc[4][8][4];
#pragma unroll
    for (int mi = 0; mi < 4; mi++)
#pragma unroll
        for (int ni = 0; ni < 8; ni++)
#pragma unroll
            for (int r = 0; r < 4; r++) acc[mi][ni][r] = 0.0f;

    // prologue: fill both stages (fill #0 of each)
    load_stage(tid, sbase + OFF_TILES + 0 * STAGE_BYTES, bm, bn, 0);
    cp_async_mbar_arrive(sbase + OFF_FULL + 8 * 0);
    load_stage(tid, sbase + OFF_TILES + 1 * STAGE_BYTES, bm, bn, BK);
    cp_async_mbar_arrive(sbase + OFF_FULL + 8 * 1);

    // per-lane ldmatrix address components (swizzle XOR constant per lane:
    // row&7 == l&7 since all added row offsets are multiples of 8)
    const uint32_t lxor = (uint32_t)((l & 7) << 4);
    const uint32_t a_row_off = (uint32_t)((wm + (l & 15)) * ROW_BYTES);
    const uint32_t a_khalf   = (uint32_t)((l >> 4) * 16);
    const uint32_t b_row_off = (uint32_t)((wn + (l & 7)) * ROW_BYTES);
    const int quad = l >> 3;
    const uint32_t b_nt_off  = (uint32_t)(((quad >> 1) * 8) * ROW_BYTES);
    const uint32_t b_khalf   = (uint32_t)((quad & 1) * 16);

    for (int it = 0; it < KITERS; it++) {
        const int s = it & 1;
        const int fl = it >> 1;

        // consumer: wait for stage `it` data (fill #fl -> parity fl&1)
        MBARRIER_WAIT(sbase + OFF_FULL + 8 * s, fl & 1);

        const uint32_t st = sbase + OFF_TILES + s * STAGE_BYTES;

#pragma unroll
        for (int sub = 0; sub < 2; sub++) {
            const uint32_t stA = st + sub * A_SUB;
            const uint32_t stB = st + A_BYTES + sub * B_SUB;
#pragma unroll
            for (int kk = 0; kk < 4; kk++) {        // k16 steps within SUBK=64
                uint32_t a[4][4], b[8][2];
#pragma unroll
                for (int mi = 0; mi < 4; mi++) {
                    uint32_t addr = stA + a_row_off + (uint32_t)(mi * 16 * ROW_BYTES)
                                  + (((uint32_t)(kk * 32) + a_khalf) ^ lxor);
                    ldsm_x4(a[mi][0], a[mi][1], a[mi][2], a[mi][3], addr);
                }
#pragma unroll
                for (int nj = 0; nj < 4; nj++) {    // each x4 covers 2 n8 tiles
                    uint32_t addr = stB + b_row_off + (uint32_t)(nj * 16 * ROW_BYTES)
                                  + b_nt_off
                                  + (((uint32_t)(kk * 32) + b_khalf) ^ lxor);
                    ldsm_x4(b[nj * 2][0], b[nj * 2][1],
                            b[nj * 2 + 1][0], b[nj * 2 + 1][1], addr);
                }
                if (sub == 1 && kk == 3)    // all smem reads of stage issued
                    MBARRIER_ARRIVE(sbase + OFF_EMPTY + 8 * s);
#pragma unroll
                for (int mi = 0; mi < 4; mi++)
#pragma unroll
                    for (int ni = 0; ni < 8; ni++)
                        mma16816(acc[mi][ni][0], acc[mi][ni][1],
                                 acc[mi][ni][2], acc[mi][ni][3],
                                 a[mi][0], a[mi][1], a[mi][2], a[mi][3],
                                 b[ni][0], b[ni][1]);
            }
        }

        // producer: refill this stage for iteration it+2 (fill #fl+1)
        if (it + 2 < KITERS) {
            // wait until ALL warps consumed fill #fl (completion #fl -> parity fl&1)
            MBARRIER_WAIT(sbase + OFF_EMPTY + 8 * s, fl & 1);
            load_stage(tid, sbase + OFF_TILES + s * STAGE_BYTES, bm, bn,
                       (it + 2) * BK);
            cp_async_mbar_arrive(sbase + OFF_FULL + 8 * s);
        }
    }

    __syncthreads();   // converge before epilogue

    // epilogue: scale/bias from smem, direct 8B stores
    const float* s_scale = reinterpret_cast<const float*>(smem + OFF_SCALE);
    const float* s_bias  = reinterpret_cast<const float*>(smem + OFF_BIAS);
    const int row0 = bm + wm + (l >> 2);
    const int col0 = wn + (l & 3) * 2;

#pragma unroll
    for (int mi = 0; mi < 4; mi++) {
#pragma unroll
        for (int ni = 0; ni < 8; ni++) {
            const int n = col0 + ni * 8;
            const float s0 = s_scale[n], s1 = s_scale[n + 1];
            const float b0 = s_bias[n],  b1 = s_bias[n + 1];
            float* p0 = out + (size_t)(row0 + mi * 16) * N_TOT + bn + n;
            float* p1 = p0 + 8 * N_TOT;
            float2 v0 = make_float2(fmaf(acc[mi][ni][0], s0, b0),
                                    fmaf(acc[mi][ni][1], s1, b1));
            float2 v1 = make_float2(fmaf(acc[mi][ni][2], s0, b0),
                                    fmaf(acc[mi][ni][3], s1, b1));
            *reinterpret_cast<float2*>(p0) = v0;
            *reinterpret_cast<float2*>(p1) = v1;
        }
    }
}

// ---------------------------------------------------------------------------
// launch
// ---------------------------------------------------------------------------
extern "C" void kernel_launch(void* const* d_in, const int* in_sizes, int n_in,
                              void* d_out, int out_size) {
    const float* x     = (const float*)d_in[0];
    const int*   w_q   = (const int*)d_in[1];
    const float* scale = (const float*)d_in[2];
    const float* bias  = (const float*)d_in[3];
    float* out = (float*)d_out;

    {
        int total = N4X + N4W;
        convert_all_kernel<<<(total + 255) / 256, 256>>>(x, w_q);
    }
    {
        static bool attr_set = false;
        if (!attr_set) {
            cudaFuncSetAttribute(qgemm_mma_kernel,
                                 cudaFuncAttributeMaxDynamicSharedMemorySize, SMEM_TOTAL);
            attr_set = true;
        }
        dim3 grid(N_TOT / BN, M_TOT / BM);  // (16, 64): x-fast shares A tiles in L2
        qgemm_mma_kernel<<<grid, NTHREADS, SMEM_TOTAL>>>(scale, bias, out);
    }
}

// round 13
// speedup vs baseline: 1.5393x; 1.5393x over previous
#include <cuda_runtime.h>
#include <cuda_fp16.h>
#include <cstdint>

static constexpr int M_TOT = 8192;   // B * S
static constexpr int N_TOT = 4096;   // D_OUT
static constexpr int K_TOT = 4096;   // D_IN

static constexpr int BM = 128;
static constexpr int BN = 256;
static constexpr int BK = 64;
static constexpr int STAGES = 4;
static constexpr int KITERS = K_TOT / BK;          // 64
static constexpr int ROW_BYTES = BK * 2;           // 128 B rows (SW128 atom)
static constexpr int A_BYTES = BM * ROW_BYTES;     // 16384
static constexpr int B_BYTES = BN * ROW_BYTES;     // 32768
static constexpr int STAGE_BYTES = A_BYTES + B_BYTES;  // 49152

static constexpr int NTHREADS = 256;               // 8 warps, 64x64 warp tiles

static constexpr int OFF_FULL  = 0;                // 4 mbarriers (8B)
static constexpr int OFF_EMPTY = 64;               // 4 mbarriers (8B)
static constexpr int OFF_SCALE = 1024;             // 256 f32
static constexpr int OFF_BIAS  = 2048;             // 256 f32
static constexpr int OFF_TILES = 3072;
static constexpr int SMEM_TOTAL = OFF_TILES + STAGES * STAGE_BYTES;  // 199680

// Scratch fp16 operands (allocation-free rule: __device__ globals)
__device__ __align__(16) __half g_xh[(size_t)M_TOT * K_TOT];   // 64 MiB
__device__ __align__(16) __half g_wh[(size_t)N_TOT * K_TOT];   // 32 MiB

// ---------------------------------------------------------------------------
// helpers
// ---------------------------------------------------------------------------
__device__ __forceinline__ uint32_t smem_u32(const void* p) {
    uint32_t a;
    asm("{ .reg .u64 t; cvta.to.shared.u64 t, %1; cvt.u32.u64 %0, t; }" : "=r"(a) : "l"(p));
    return a;
}
__device__ __forceinline__ uint32_t swz(uint32_t byte_off) {
    return byte_off ^ ((byte_off >> 3) & 0x70);
}
__device__ __forceinline__ void cp_async16(uint32_t saddr, const void* gptr) {
    asm volatile("cp.async.cg.shared.global [%0], [%1], 16;" :: "r"(saddr), "l"(gptr));
}
// arrive on mbar when ALL prior cp.async of this thread have completed
__device__ __forceinline__ void cp_async_mbar_arrive(uint32_t mbar) {
    asm volatile("cp.async.mbarrier.arrive.noinc.shared.b64 [%0];" :: "r"(mbar) : "memory");
}
#define MBARRIER_INIT(a, c) \
    asm volatile("mbarrier.init.shared.b64 [%0], %1;" :: "r"(a), "r"(c) : "memory")
#define MBARRIER_ARRIVE(a) \
    asm volatile("mbarrier.arrive.release.cta.shared::cta.b64 _, [%0];" :: "r"(a) : "memory")
#define MBARRIER_WAIT(a, ph) do {                                              \
    asm volatile("{\n\t.reg .pred P;\n\tWL_%=:\n\t"                            \
        "mbarrier.try_wait.parity.acquire.cta.shared::cta.b64 P, [%0], %1, 0x989680;\n\t" \
        "@P bra.uni WD_%=;\n\tbra.uni WL_%=;\n\tWD_%=:\n\t}"                   \
        :: "r"(a), "r"(ph) : "memory");                                        \
} while (0)

__device__ __forceinline__ void ldsm_x4(uint32_t& r0, uint32_t& r1,
                                        uint32_t& r2, uint32_t& r3, uint32_t addr) {
    asm volatile("ldmatrix.sync.aligned.m8n8.x4.shared.b16 {%0,%1,%2,%3}, [%4];"
                 : "=r"(r0), "=r"(r1), "=r"(r2), "=r"(r3) : "r"(addr));
}
__device__ __forceinline__ void mma16816(float& c0, float& c1, float& c2, float& c3,
                                         uint32_t a0, uint32_t a1, uint32_t a2, uint32_t a3,
                                         uint32_t b0, uint32_t b1) {
    asm volatile(
        "mma.sync.aligned.m16n8k16.row.col.f32.f16.f16.f32 "
        "{%0,%1,%2,%3}, {%4,%5,%6,%7}, {%8,%9}, {%0,%1,%2,%3};"
        : "+f"(c0), "+f"(c1), "+f"(c2), "+f"(c3)
        : "r"(a0), "r"(a1), "r"(a2), "r"(a3), "r"(b0), "r"(b1));
}

// ---------------------------------------------------------------------------
// fused conversion kernel: fp32->fp16 (x) and int32->fp16 (w) in one launch
// ---------------------------------------------------------------------------
static constexpr int N4X = (M_TOT * K_TOT) / 4;    // 8388608
static constexpr int N4W = (N_TOT * K_TOT) / 4;    // 4194304

__global__ void convert_all_kernel(const float* __restrict__ x,
                                   const int* __restrict__ w) {
    int i = blockIdx.x * blockDim.x + threadIdx.x;
    if (i < N4X) {
        float4 v = reinterpret_cast<const float4*>(x)[i];
        __half2* dst = reinterpret_cast<__half2*>(g_xh);
        dst[2 * i]     = __floats2half2_rn(v.x, v.y);
        dst[2 * i + 1] = __floats2half2_rn(v.z, v.w);
    } else {
        int j = i - N4X;
        if (j < N4W) {
            int4 v = reinterpret_cast<const int4*>(w)[j];
            __half2* dst = reinterpret_cast<__half2*>(g_wh);
            dst[2 * j]     = __halves2half2(__int2half_rn(v.x), __int2half_rn(v.y));
            dst[2 * j + 1] = __halves2half2(__int2half_rn(v.z), __int2half_rn(v.w));
        }
    }
}

// ---------------------------------------------------------------------------
// stage loader: 3072 x 16B cp.async (A: 1024, B: 2048 chunks), SW128 swizzle
// ---------------------------------------------------------------------------
__device__ __forceinline__ void load_stage(int tid, uint32_t stage_base,
                                           int bm, int bn, int k0) {
#pragma unroll
    for (int i = 0; i < 12; i++) {
        int idx = tid + i * NTHREADS;
        if (idx < 1024) {                     // A
            int r   = idx >> 3;
            int c16 = idx & 7;
            uint32_t sw = swz((uint32_t)(r * ROW_BYTES + c16 * 16));
            cp_async16(stage_base + sw,
                       g_xh + (size_t)(bm + r) * K_TOT + k0 + c16 * 8);
        } else {                              // B
            int j   = idx - 1024;
            int r   = j >> 3;
            int c16 = j & 7;
            uint32_t sw = swz((uint32_t)(r * ROW_BYTES + c16 * 16));
            cp_async16(stage_base + A_BYTES + sw,
                       g_wh + (size_t)(bn + r) * K_TOT + k0 + c16 * 8);
        }
    }
}

// ---------------------------------------------------------------------------
// GEMM: 128x256 block tile, BK=64, 4-stage mbarrier producer/consumer —
//       no __syncthreads in the mainloop; the 4th stage gives the producer
//       TWO full iterations of empty-wait slack (R12 showed distance-0
//       empty-waits serialize the pipeline), so all waits are fast-path.
// ---------------------------------------------------------------------------
__global__ __launch_bounds__(NTHREADS, 1)
void qgemm_mma_kernel(const float* __restrict__ scale,
                      const float* __restrict__ bias,
                      float* __restrict__ out) {
    extern __shared__ __align__(1024) char smem[];
    const uint32_t sbase = smem_u32(smem);
    const int tid = threadIdx.x;
    const int wid = tid >> 5;
    const int l = tid & 31;

    const int bm = blockIdx.y * BM;
    const int bn = blockIdx.x * BN;
    const int wm = (wid & 1) * 64;     // warp M offset (0 or 64)
    const int wn = (wid >> 1) * 64;    // warp N offset (0,64,128,192)

    // init mbarriers (one thread), then converge once
    if (tid == 0) {
#pragma unroll
        for (int s = 0; s < STAGES; s++) {
            MBARRIER_INIT(sbase + OFF_FULL + 8 * s, NTHREADS);
            MBARRIER_INIT(sbase + OFF_EMPTY + 8 * s, NTHREADS);
        }
    }
    // scale/bias for this N tile into smem
    reinterpret_cast<float*>(smem + OFF_SCALE)[tid] = scale[bn + tid];
    reinterpret_cast<float*>(smem + OFF_BIAS)[tid]  = bias[bn + tid];
    __syncthreads();

    float acc[4][8][4];
#pragma unroll
    for (int mi = 0; mi < 4; mi++)
#pragma unroll
        for (int ni = 0; ni < 8; ni++)
#pragma unroll
            for (int r = 0; r < 4; r++) acc[mi][ni][r] = 0.0f;

    // prologue: fill stages 0..2 (fill #0 of each)
    load_stage(tid, sbase + OFF_TILES + 0 * STAGE_BYTES, bm, bn, 0);
    cp_async_mbar_arrive(sbase + OFF_FULL + 8 * 0);
    load_stage(tid, sbase + OFF_TILES + 1 * STAGE_BYTES, bm, bn, BK);
    cp_async_mbar_arrive(sbase + OFF_FULL + 8 * 1);
    load_stage(tid, sbase + OFF_TILES + 2 * STAGE_BYTES, bm, bn, 2 * BK);
    cp_async_mbar_arrive(sbase + OFF_FULL + 8 * 2);

    // per-lane ldmatrix address components (swizzle XOR constant per lane:
    // row&7 == l&7 since all added row offsets are multiples of 8)
    const uint32_t lxor = (uint32_t)((l & 7) << 4);
    const uint32_t a_row_off = (uint32_t)((wm + (l & 15)) * ROW_BYTES);
    const uint32_t a_khalf   = (uint32_t)((l >> 4) * 16);
    const uint32_t b_row_off = (uint32_t)((wn + (l & 7)) * ROW_BYTES);
    const int quad = l >> 3;
    const uint32_t b_nt_off  = (uint32_t)(((quad >> 1) * 8) * ROW_BYTES);
    const uint32_t b_khalf   = (uint32_t)((quad & 1) * 16);

    for (int it = 0; it < KITERS; it++) {
        const int s = it & 3;
        const int fl = it >> 2;

        // consumer: wait for stage `it` data (fill #fl -> parity fl&1)
        MBARRIER_WAIT(sbase + OFF_FULL + 8 * s, fl & 1);

        const uint32_t stA = sbase + OFF_TILES + s * STAGE_BYTES;
        const uint32_t stB = stA + A_BYTES;

#pragma unroll
        for (int kk = 0; kk < 4; kk++) {            // k16 steps within BK=64
            uint32_t a[4][4], b[8][2];
#pragma unroll
            for (int mi = 0; mi < 4; mi++) {
                uint32_t addr = stA + a_row_off + (uint32_t)(mi * 16 * ROW_BYTES)
                              + (((uint32_t)(kk * 32) + a_khalf) ^ lxor);
                ldsm_x4(a[mi][0], a[mi][1], a[mi][2], a[mi][3], addr);
            }
#pragma unroll
            for (int nj = 0; nj < 4; nj++) {        // each x4 covers 2 n8 tiles
                uint32_t addr = stB + b_row_off + (uint32_t)(nj * 16 * ROW_BYTES)
                              + b_nt_off
                              + (((uint32_t)(kk * 32) + b_khalf) ^ lxor);
                ldsm_x4(b[nj * 2][0], b[nj * 2][1],
                        b[nj * 2 + 1][0], b[nj * 2 + 1][1], addr);
            }
            if (kk == 3)      // all smem reads of this stage issued
                MBARRIER_ARRIVE(sbase + OFF_EMPTY + 8 * s);
#pragma unroll
            for (int mi = 0; mi < 4; mi++)
#pragma unroll
                for (int ni = 0; ni < 8; ni++)
                    mma16816(acc[mi][ni][0], acc[mi][ni][1],
                             acc[mi][ni][2], acc[mi][ni][3],
                             a[mi][0], a[mi][1], a[mi][2], a[mi][3],
                             b[ni][0], b[ni][1]);
        }

        // producer: refill stage for iteration it+3 (fill #(it+3)/4)
        const int nxt = it + 3;
        if (nxt < KITERS) {
            const int s2 = nxt & 3;
            const int f2 = nxt >> 2;
            if (nxt >= STAGES)  // wait for consumers of the previous fill (f2-1)
                MBARRIER_WAIT(sbase + OFF_EMPTY + 8 * s2, (f2 - 1) & 1);
            load_stage(tid, sbase + OFF_TILES + s2 * STAGE_BYTES, bm, bn, nxt * BK);
            cp_async_mbar_arrive(sbase + OFF_FULL + 8 * s2);
        }
    }

    __syncthreads();   // converge before epilogue

    // epilogue: scale/bias from smem, direct 8B stores
    const float* s_scale = reinterpret_cast<const float*>(smem + OFF_SCALE);
    const float* s_bias  = reinterpret_cast<const float*>(smem + OFF_BIAS);
    const int row0 = bm + wm + (l >> 2);
    const int col0 = wn + (l & 3) * 2;

#pragma unroll
    for (int mi = 0; mi < 4; mi++) {
#pragma unroll
        for (int ni = 0; ni < 8; ni++) {
            const int n = col0 + ni * 8;
            const float s0 = s_scale[n], s1 = s_scale[n + 1];
            const float b0 = s_bias[n],  b1 = s_bias[n + 1];
            float* p0 = out + (size_t)(row0 + mi * 16) * N_TOT + bn + n;
            float* p1 = p0 + 8 * N_TOT;
            float2 v0 = make_float2(fmaf(acc[mi][ni][0], s0, b0),
                                    fmaf(acc[mi][ni][1], s1, b1));
            float2 v1 = make_float2(fmaf(acc[mi][ni][2], s0, b0),
                                    fmaf(acc[mi][ni][3], s1, b1));
            *reinterpret_cast<float2*>(p0) = v0;
            *reinterpret_cast<float2*>(p1) = v1;
        }
    }
}

// ---------------------------------------------------------------------------
// launch
// ---------------------------------------------------------------------------
extern "C" void kernel_launch(void* const* d_in, const int* in_sizes, int n_in,
                              void* d_out, int out_size) {
    const float* x     = (const float*)d_in[0];
    const int*   w_q   = (const int*)d_in[1];
    const float* scale = (const float*)d_in[2];
    const float* bias  = (const float*)d_in[3];
    float* out = (float*)d_out;

    {
        int total = N4X + N4W;
        convert_all_kernel<<<(total + 255) / 256, 256>>>(x, w_q);
    }
    {
        static bool attr_set = false;
        if (!attr_set) {
            cudaFuncSetAttribute(qgemm_mma_kernel,
                                 cudaFuncAttributeMaxDynamicSharedMemorySize, SMEM_TOTAL);
            attr_set = true;
        }
        dim3 grid(N_TOT / BN, M_TOT / BM);  // (16, 64): x-fast shares A tiles in L2
        qgemm_mma_kernel<<<grid, NTHREADS, SMEM_TOTAL>>>(scale, bias, out);
    }
}

// round 14
// speedup vs baseline: 1.5796x; 1.0262x over previous
#include <cuda_runtime.h>
#include <cuda_fp16.h>
#include <cstdint>

static constexpr int M_TOT = 8192;   // B * S
static constexpr int N_TOT = 4096;   // D_OUT
static constexpr int K_TOT = 4096;   // D_IN

static constexpr int BM = 128;
static constexpr int BN = 256;
static constexpr int BK = 64;
static constexpr int STAGES = 4;
static constexpr int KITERS = K_TOT / BK;          // 64
static constexpr int ROW_BYTES = BK * 2;           // 128 B rows (SW128 atom)
static constexpr int A_BYTES = BM * ROW_BYTES;     // 16384
static constexpr int B_BYTES = BN * ROW_BYTES;     // 32768
static constexpr int STAGE_BYTES = A_BYTES + B_BYTES;  // 49152

static constexpr int NTHREADS = 256;               // 8 warps, 64x64 warp tiles
static constexpr int GRID    = 148;                // persistent: one CTA per SM
static constexpr int NT_N    = N_TOT / BN;         // 16 tiles along N
static constexpr int NTILES  = (M_TOT / BM) * NT_N;  // 1024

static constexpr int OFF_FULL  = 0;                // 4 mbarriers (8B)
static constexpr int OFF_EMPTY = 64;               // 4 mbarriers (8B)
static constexpr int OFF_TILES = 1024;
static constexpr int SMEM_TOTAL = OFF_TILES + STAGES * STAGE_BYTES;  // 197632

// Scratch fp16 operands (allocation-free rule: __device__ globals)
__device__ __align__(16) __half g_xh[(size_t)M_TOT * K_TOT];   // 64 MiB
__device__ __align__(16) __half g_wh[(size_t)N_TOT * K_TOT];   // 32 MiB

// ---------------------------------------------------------------------------
// helpers
// ---------------------------------------------------------------------------
__device__ __forceinline__ uint32_t smem_u32(const void* p) {
    uint32_t a;
    asm("{ .reg .u64 t; cvta.to.shared.u64 t, %1; cvt.u32.u64 %0, t; }" : "=r"(a) : "l"(p));
    return a;
}
__device__ __forceinline__ uint32_t swz(uint32_t byte_off) {
    return byte_off ^ ((byte_off >> 3) & 0x70);
}
__device__ __forceinline__ void cp_async16(uint32_t saddr, const void* gptr) {
    asm volatile("cp.async.cg.shared.global [%0], [%1], 16;" :: "r"(saddr), "l"(gptr));
}
// arrive on mbar when ALL prior cp.async of this thread have completed
__device__ __forceinline__ void cp_async_mbar_arrive(uint32_t mbar) {
    asm volatile("cp.async.mbarrier.arrive.noinc.shared.b64 [%0];" :: "r"(mbar) : "memory");
}
#define MBARRIER_INIT(a, c) \
    asm volatile("mbarrier.init.shared.b64 [%0], %1;" :: "r"(a), "r"(c) : "memory")
#define MBARRIER_ARRIVE(a) \
    asm volatile("mbarrier.arrive.release.cta.shared::cta.b64 _, [%0];" :: "r"(a) : "memory")
#define MBARRIER_WAIT(a, ph) do {                                              \
    asm volatile("{\n\t.reg .pred P;\n\tWL_%=:\n\t"                            \
        "mbarrier.try_wait.parity.acquire.cta.shared::cta.b64 P, [%0], %1, 0x989680;\n\t" \
        "@P bra.uni WD_%=;\n\tbra.uni WL_%=;\n\tWD_%=:\n\t}"                   \
        :: "r"(a), "r"(ph) : "memory");                                        \
} while (0)

__device__ __forceinline__ void ldsm_x4(uint32_t& r0, uint32_t& r1,
                                        uint32_t& r2, uint32_t& r3, uint32_t addr) {
    asm volatile("ldmatrix.sync.aligned.m8n8.x4.shared.b16 {%0,%1,%2,%3}, [%4];"
                 : "=r"(r0), "=r"(r1), "=r"(r2), "=r"(r3) : "r"(addr));
}
__device__ __forceinline__ void mma16816(float& c0, float& c1, float& c2, float& c3,
                                         uint32_t a0, uint32_t a1, uint32_t a2, uint32_t a3,
                                         uint32_t b0, uint32_t b1) {
    asm volatile(
        "mma.sync.aligned.m16n8k16.row.col.f32.f16.f16.f32 "
        "{%0,%1,%2,%3}, {%4,%5,%6,%7}, {%8,%9}, {%0,%1,%2,%3};"
        : "+f"(c0), "+f"(c1), "+f"(c2), "+f"(c3)
        : "r"(a0), "r"(a1), "r"(a2), "r"(a3), "r"(b0), "r"(b1));
}

// ---------------------------------------------------------------------------
// fused conversion kernel: fp32->fp16 (x) and int32->fp16 (w) in one launch
// ---------------------------------------------------------------------------
static constexpr int N4X = (M_TOT * K_TOT) / 4;    // 8388608
static constexpr int N4W = (N_TOT * K_TOT) / 4;    // 4194304

__global__ void convert_all_kernel(const float* __restrict__ x,
                                   const int* __restrict__ w) {
    int i = blockIdx.x * blockDim.x + threadIdx.x;
    if (i < N4X) {
        float4 v = reinterpret_cast<const float4*>(x)[i];
        __half2* dst = reinterpret_cast<__half2*>(g_xh);
        dst[2 * i]     = __floats2half2_rn(v.x, v.y);
        dst[2 * i + 1] = __floats2half2_rn(v.z, v.w);
    } else {
        int j = i - N4X;
        if (j < N4W) {
            int4 v = reinterpret_cast<const int4*>(w)[j];
            __half2* dst = reinterpret_cast<__half2*>(g_wh);
            dst[2 * j]     = __halves2half2(__int2half_rn(v.x), __int2half_rn(v.y));
            dst[2 * j + 1] = __halves2half2(__int2half_rn(v.z), __int2half_rn(v.w));
        }
    }
}

// ---------------------------------------------------------------------------
// stage loader: 3072 x 16B cp.async (A: 1024, B: 2048 chunks), SW128 swizzle
// ---------------------------------------------------------------------------
__device__ __forceinline__ void load_stage(int tid, uint32_t stage_base,
                                           int bm, int bn, int k0) {
#pragma unroll
    for (int i = 0; i < 12; i++) {
        int idx = tid + i * NTHREADS;
        if (idx < 1024) {                     // A
            int r   = idx >> 3;
            int c16 = idx & 7;
            uint32_t sw = swz((uint32_t)(r * ROW_BYTES + c16 * 16));
            cp_async16(stage_base + sw,
                       g_xh + (size_t)(bm + r) * K_TOT + k0 + c16 * 8);
        } else {                              // B
            int j   = idx - 1024;
            int r   = j >> 3;
            int c16 = j & 7;
            uint32_t sw = swz((uint32_t)(r * ROW_BYTES + c16 * 16));
            cp_async16(stage_base + A_BYTES + sw,
                       g_wh + (size_t)(bn + r) * K_TOT + k0 + c16 * 8);
        }
    }
}

// load for GLOBAL iteration g of this CTA's tile stream; false if past the end
__device__ __forceinline__ void load_iter(int tid, uint32_t sbase, int tile0, int g) {
    const int lt = g >> 6;                    // local tile index
    const int t2 = tile0 + lt * GRID;         // global tile id
    if (t2 >= NTILES) return;
    const int bm2 = (t2 >> 4) * BM;           // t2 / NT_N
    const int bn2 = (t2 & 15) * BN;           // t2 % NT_N
    const int k0  = (g & 63) * BK;
    load_stage(tid, sbase + OFF_TILES + (g & 3) * STAGE_BYTES, bm2, bn2, k0);
    cp_async_mbar_arrive(sbase + OFF_FULL + 8 * (g & 3));
}

// ---------------------------------------------------------------------------
// Persistent GEMM: grid=148, each CTA streams ~7 tiles (128x256 each) through
// ONE continuous 4-stage mbarrier pipeline indexed by a global iteration g.
// Stage fills cross tile boundaries, so the pipeline never drains: prologue
// is paid once per CTA, and epilogues overlap with the next tile's prefetch.
// ---------------------------------------------------------------------------
__global__ __launch_bounds__(NTHREADS, 1)
void qgemm_mma_kernel(const float* __restrict__ scale,
                      const float* __restrict__ bias,
                      float* __restrict__ out) {
    extern __shared__ __align__(1024) char smem[];
    const uint32_t sbase = smem_u32(smem);
    const int tid = threadIdx.x;
    const int wid = tid >> 5;
    const int l = tid & 31;
    const int tile0 = blockIdx.x;

    const int wm = (wid & 1) * 64;     // warp M offset (0 or 64)
    const int wn = (wid >> 1) * 64;    // warp N offset (0,64,128,192)

    if (tid == 0) {
#pragma unroll
        for (int s = 0; s < STAGES; s++) {
            MBARRIER_INIT(sbase + OFF_FULL + 8 * s, NTHREADS);
            MBARRIER_INIT(sbase + OFF_EMPTY + 8 * s, NTHREADS);
        }
    }
    __syncthreads();

    float acc[4][8][4];
#pragma unroll
    for (int mi = 0; mi < 4; mi++)
#pragma unroll
        for (int ni = 0; ni < 8; ni++)
#pragma unroll
            for (int r = 0; r < 4; r++) acc[mi][ni][r] = 0.0f;

    // prologue: fill the pipeline for global iterations 0..2 (first tile)
    load_iter(tid, sbase, tile0, 0);
    load_iter(tid, sbase, tile0, 1);
    load_iter(tid, sbase, tile0, 2);

    // per-lane ldmatrix address components (swizzle XOR constant per lane:
    // row&7 == l&7 since all added row offsets are multiples of 8)
    const uint32_t lxor = (uint32_t)((l & 7) << 4);
    const uint32_t a_row_off = (uint32_t)((wm + (l & 15)) * ROW_BYTES);
    const uint32_t a_khalf   = (uint32_t)((l >> 4) * 16);
    const uint32_t b_row_off = (uint32_t)((wn + (l & 7)) * ROW_BYTES);
    const int quad = l >> 3;
    const uint32_t b_nt_off  = (uint32_t)(((quad >> 1) * 8) * ROW_BYTES);
    const uint32_t b_khalf   = (uint32_t)((quad & 1) * 16);

    int g = 0;
    for (int t2 = tile0; t2 < NTILES; t2 += GRID) {
        const int bm = (t2 >> 4) * BM;
        const int bn = (t2 & 15) * BN;

        for (int kit = 0; kit < KITERS; kit++, g++) {
            const int s = g & 3;
            const int fl = g >> 2;

            // consumer: wait for global iteration g's stage (fill #fl)
            MBARRIER_WAIT(sbase + OFF_FULL + 8 * s, fl & 1);

            const uint32_t stA = sbase + OFF_TILES + s * STAGE_BYTES;
            const uint32_t stB = stA + A_BYTES;

#pragma unroll
            for (int kk = 0; kk < 4; kk++) {        // k16 steps within BK=64
                uint32_t a[4][4], b[8][2];
#pragma unroll
                for (int mi = 0; mi < 4; mi++) {
                    uint32_t addr = stA + a_row_off + (uint32_t)(mi * 16 * ROW_BYTES)
                                  + (((uint32_t)(kk * 32) + a_khalf) ^ lxor);
                    ldsm_x4(a[mi][0], a[mi][1], a[mi][2], a[mi][3], addr);
                }
#pragma unroll
                for (int nj = 0; nj < 4; nj++) {    // each x4 covers 2 n8 tiles
                    uint32_t addr = stB + b_row_off + (uint32_t)(nj * 16 * ROW_BYTES)
                                  + b_nt_off
                                  + (((uint32_t)(kk * 32) + b_khalf) ^ lxor);
                    ldsm_x4(b[nj * 2][0], b[nj * 2][1],
                            b[nj * 2 + 1][0], b[nj * 2 + 1][1], addr);
                }
                if (kk == 3)      // all smem reads of this stage issued
                    MBARRIER_ARRIVE(sbase + OFF_EMPTY + 8 * s);
#pragma unroll
                for (int mi = 0; mi < 4; mi++)
#pragma unroll
                    for (int ni = 0; ni < 8; ni++)
                        mma16816(acc[mi][ni][0], acc[mi][ni][1],
                                 acc[mi][ni][2], acc[mi][ni][3],
                                 a[mi][0], a[mi][1], a[mi][2], a[mi][3],
                                 b[ni][0], b[ni][1]);
            }

            // producer: fill global iteration g+3 (may belong to the NEXT tile)
            const int gn = g + 3;
            {
                const int lt2 = gn >> 6;
                if (tile0 + lt2 * GRID < NTILES) {
                    const int s2 = gn & 3;
                    const int f2 = gn >> 2;
                    if (gn >= STAGES)   // wait consumers of fill f2-1 (done at g-1)
                        MBARRIER_WAIT(sbase + OFF_EMPTY + 8 * s2, (f2 - 1) & 1);
                    load_iter(tid, sbase, tile0, gn);
                }
            }
        }

        // epilogue for tile (bm, bn): acc regs only, scale/bias via read-only
        // cache — no smem, no barrier; overlaps the next tile's prefetch.
        const int row0 = bm + wm + (l >> 2);
        const int col0 = wn + (l & 3) * 2;
#pragma unroll
        for (int mi = 0; mi < 4; mi++) {
#pragma unroll
            for (int ni = 0; ni < 8; ni++) {
                const int n = bn + col0 + ni * 8;
                const float s0 = __ldg(scale + n),     s1 = __ldg(scale + n + 1);
                const float b0 = __ldg(bias + n),      b1 = __ldg(bias + n + 1);
                float* p0 = out + (size_t)(row0 + mi * 16) * N_TOT + n;
                float* p1 = p0 + 8 * N_TOT;
                float2 v0 = make_float2(fmaf(acc[mi][ni][0], s0, b0),
                                        fmaf(acc[mi][ni][1], s1, b1));
                float2 v1 = make_float2(fmaf(acc[mi][ni][2], s0, b0),
                                        fmaf(acc[mi][ni][3], s1, b1));
                *reinterpret_cast<float2*>(p0) = v0;
                *reinterpret_cast<float2*>(p1) = v1;
                acc[mi][ni][0] = 0.0f; acc[mi][ni][1] = 0.0f;
                acc[mi][ni][2] = 0.0f; acc[mi][ni][3] = 0.0f;
            }
        }
    }
}

// ---------------------------------------------------------------------------
// launch
// ---------------------------------------------------------------------------
extern "C" void kernel_launch(void* const* d_in, const int* in_sizes, int n_in,
                              void* d_out, int out_size) {
    const float* x     = (const float*)d_in[0];
    const int*   w_q   = (const int*)d_in[1];
    const float* scale = (const float*)d_in[2];
    const float* bias  = (const float*)d_in[3];
    float* out = (float*)d_out;

    {
        int total = N4X + N4W;
        convert_all_kernel<<<(total + 255) / 256, 256>>>(x, w_q);
    }
    {
        static bool attr_set = false;
        if (!attr_set) {
            cudaFuncSetAttribute(qgemm_mma_kernel,
                                 cudaFuncAttributeMaxDynamicSharedMemorySize, SMEM_TOTAL);
            attr_set = true;
        }
        qgemm_mma_kernel<<<GRID, NTHREADS, SMEM_TOTAL>>>(scale, bias, out);
    }
}

// round 15
// speedup vs baseline: 1.5857x; 1.0039x over previous
#include <cuda_runtime.h>
#include <cuda_fp16.h>
#include <cstdint>

static constexpr int M_TOT = 8192;   // B * S
static constexpr int N_TOT = 4096;   // D_OUT
static constexpr int K_TOT = 4096;   // D_IN

static constexpr int BM = 128;
static constexpr int BN = 256;
static constexpr int BK = 64;
static constexpr int STAGES = 4;
static constexpr int KITERS = K_TOT / BK;          // 64
static constexpr int ROW_BYTES = BK * 2;           // 128 B rows (SW128 atom)
static constexpr int A_BYTES = BM * ROW_BYTES;     // 16384
static constexpr int B_BYTES = BN * ROW_BYTES;     // 32768
static constexpr int STAGE_BYTES = A_BYTES + B_BYTES;  // 49152

static constexpr int NTHREADS = 256;               // 8 warps, 64x64 warp tiles
static constexpr int GRID    = 148;                // persistent: one CTA per SM
static constexpr int NT_N    = N_TOT / BN;         // 16 tiles along N
static constexpr int NTILES  = (M_TOT / BM) * NT_N;  // 1024

static constexpr int OFF_FULL  = 0;                // 4 mbarriers (8B)
static constexpr int OFF_EMPTY = 64;               // 4 mbarriers (8B)
static constexpr int OFF_TILES = 1024;
static constexpr int SMEM_TOTAL = OFF_TILES + STAGES * STAGE_BYTES;  // 197632

static constexpr unsigned STAGGER_CYC = 1200;      // ~half an iteration

// Scratch fp16 operands (allocation-free rule: __device__ globals)
__device__ __align__(16) __half g_xh[(size_t)M_TOT * K_TOT];   // 64 MiB
__device__ __align__(16) __half g_wh[(size_t)N_TOT * K_TOT];   // 32 MiB

// ---------------------------------------------------------------------------
// helpers
// ---------------------------------------------------------------------------
__device__ __forceinline__ uint32_t smem_u32(const void* p) {
    uint32_t a;
    asm("{ .reg .u64 t; cvta.to.shared.u64 t, %1; cvt.u32.u64 %0, t; }" : "=r"(a) : "l"(p));
    return a;
}
__device__ __forceinline__ uint32_t swz(uint32_t byte_off) {
    return byte_off ^ ((byte_off >> 3) & 0x70);
}
__device__ __forceinline__ void cp_async16(uint32_t saddr, const void* gptr) {
    asm volatile("cp.async.cg.shared.global [%0], [%1], 16;" :: "r"(saddr), "l"(gptr));
}
// arrive on mbar when ALL prior cp.async of this thread have completed
__device__ __forceinline__ void cp_async_mbar_arrive(uint32_t mbar) {
    asm volatile("cp.async.mbarrier.arrive.noinc.shared.b64 [%0];" :: "r"(mbar) : "memory");
}
#define MBARRIER_INIT(a, c) \
    asm volatile("mbarrier.init.shared.b64 [%0], %1;" :: "r"(a), "r"(c) : "memory")
#define MBARRIER_ARRIVE(a) \
    asm volatile("mbarrier.arrive.release.cta.shared::cta.b64 _, [%0];" :: "r"(a) : "memory")
#define MBARRIER_WAIT(a, ph) do {                                              \
    asm volatile("{\n\t.reg .pred P;\n\tWL_%=:\n\t"                            \
        "mbarrier.try_wait.parity.acquire.cta.shared::cta.b64 P, [%0], %1, 0x989680;\n\t" \
        "@P bra.uni WD_%=;\n\tbra.uni WL_%=;\n\tWD_%=:\n\t}"                   \
        :: "r"(a), "r"(ph) : "memory");                                        \
} while (0)

__device__ __forceinline__ void ldsm_x4(uint32_t& r0, uint32_t& r1,
                                        uint32_t& r2, uint32_t& r3, uint32_t addr) {
    asm volatile("ldmatrix.sync.aligned.m8n8.x4.shared.b16 {%0,%1,%2,%3}, [%4];"
                 : "=r"(r0), "=r"(r1), "=r"(r2), "=r"(r3) : "r"(addr));
}
__device__ __forceinline__ void mma16816(float& c0, float& c1, float& c2, float& c3,
                                         uint32_t a0, uint32_t a1, uint32_t a2, uint32_t a3,
                                         uint32_t b0, uint32_t b1) {
    asm volatile(
        "mma.sync.aligned.m16n8k16.row.col.f32.f16.f16.f32 "
        "{%0,%1,%2,%3}, {%4,%5,%6,%7}, {%8,%9}, {%0,%1,%2,%3};"
        : "+f"(c0), "+f"(c1), "+f"(c2), "+f"(c3)
        : "r"(a0), "r"(a1), "r"(a2), "r"(a3), "r"(b0), "r"(b1));
}

// ---------------------------------------------------------------------------
// fused conversion kernel: fp32->fp16 (x) and int32->fp16 (w) in one launch
// ---------------------------------------------------------------------------
static constexpr int N4X = (M_TOT * K_TOT) / 4;    // 8388608
static constexpr int N4W = (N_TOT * K_TOT) / 4;    // 4194304

__global__ void convert_all_kernel(const float* __restrict__ x,
                                   const int* __restrict__ w) {
    int i = blockIdx.x * blockDim.x + threadIdx.x;
    if (i < N4X) {
        float4 v = reinterpret_cast<const float4*>(x)[i];
        __half2* dst = reinterpret_cast<__half2*>(g_xh);
        dst[2 * i]     = __floats2half2_rn(v.x, v.y);
        dst[2 * i + 1] = __floats2half2_rn(v.z, v.w);
    } else {
        int j = i - N4X;
        if (j < N4W) {
            int4 v = reinterpret_cast<const int4*>(w)[j];
            __half2* dst = reinterpret_cast<__half2*>(g_wh);
            dst[2 * j]     = __halves2half2(__int2half_rn(v.x), __int2half_rn(v.y));
            dst[2 * j + 1] = __halves2half2(__int2half_rn(v.z), __int2half_rn(v.w));
        }
    }
}

// ---------------------------------------------------------------------------
// stage loader: 3072 x 16B cp.async (A: 1024, B: 2048 chunks), SW128 swizzle
// ---------------------------------------------------------------------------
__device__ __forceinline__ void load_stage(int tid, uint32_t stage_base,
                                           int bm, int bn, int k0) {
#pragma unroll
    for (int i = 0; i < 12; i++) {
        int idx = tid + i * NTHREADS;
        if (idx < 1024) {                     // A
            int r   = idx >> 3;
            int c16 = idx & 7;
            uint32_t sw = swz((uint32_t)(r * ROW_BYTES + c16 * 16));
            cp_async16(stage_base + sw,
                       g_xh + (size_t)(bm + r) * K_TOT + k0 + c16 * 8);
        } else {                              // B
            int j   = idx - 1024;
            int r   = j >> 3;
            int c16 = j & 7;
            uint32_t sw = swz((uint32_t)(r * ROW_BYTES + c16 * 16));
            cp_async16(stage_base + A_BYTES + sw,
                       g_wh + (size_t)(bn + r) * K_TOT + k0 + c16 * 8);
        }
    }
}

// load for GLOBAL iteration g of this CTA's tile stream
__device__ __forceinline__ void load_iter(int tid, uint32_t sbase, int tile0, int g) {
    const int lt = g >> 6;                    // local tile index
    const int t2 = tile0 + lt * GRID;         // global tile id
    if (t2 >= NTILES) return;
    const int bm2 = (t2 >> 4) * BM;           // t2 / NT_N
    const int bn2 = (t2 & 15) * BN;           // t2 % NT_N
    const int k0  = (g & 63) * BK;
    load_stage(tid, sbase + OFF_TILES + (g & 3) * STAGE_BYTES, bm2, bn2, k0);
    cp_async_mbar_arrive(sbase + OFF_FULL + 8 * (g & 3));
}

// ---------------------------------------------------------------------------
// Persistent GEMM (R14) + half-iteration warp stagger: warps 4-7 (the second
// warp on each SMSP, SMSP = wid%4) start ~1200 cyc late, anti-phasing the two
// warps per SMSP so their mbarrier-wait + cp.async-issue windows interleave
// with each other's MMA bursts instead of stalling the tensor pipe together.
// ---------------------------------------------------------------------------
__global__ __launch_bounds__(NTHREADS, 1)
void qgemm_mma_kernel(const float* __restrict__ scale,
                      const float* __restrict__ bias,
                      float* __restrict__ out) {
    extern __shared__ __align__(1024) char smem[];
    const uint32_t sbase = smem_u32(smem);
    const int tid = threadIdx.x;
    const int wid = tid >> 5;
    const int l = tid & 31;
    const int tile0 = blockIdx.x;

    const int wm = (wid & 1) * 64;     // warp M offset (0 or 64)
    const int wn = (wid >> 1) * 64;    // warp N offset (0,64,128,192)

    if (tid == 0) {
#pragma unroll
        for (int s = 0; s < STAGES; s++) {
            MBARRIER_INIT(sbase + OFF_FULL + 8 * s, NTHREADS);
            MBARRIER_INIT(sbase + OFF_EMPTY + 8 * s, NTHREADS);
        }
    }
    __syncthreads();

    float acc[4][8][4];
#pragma unroll
    for (int mi = 0; mi < 4; mi++)
#pragma unroll
        for (int ni = 0; ni < 8; ni++)
#pragma unroll
            for (int r = 0; r < 4; r++) acc[mi][ni][r] = 0.0f;

    // prologue: fill the pipeline for global iterations 0..2 (first tile)
    load_iter(tid, sbase, tile0, 0);
    load_iter(tid, sbase, tile0, 1);
    load_iter(tid, sbase, tile0, 2);

    // stagger: second warp on each SMSP starts ~half an iteration late.
    // (After prologue issue so every thread's cp.async slices are in flight.)
    if (wid >= 4) {
        uint32_t t0, t1;
        asm volatile("mov.u32 %0, %%clock;" : "=r"(t0));
        do { asm volatile("mov.u32 %0, %%clock;" : "=r"(t1)); }
        while (t1 - t0 < STAGGER_CYC);
    }

    // per-lane ldmatrix address components (swizzle XOR constant per lane:
    // row&7 == l&7 since all added row offsets are multiples of 8)
    const uint32_t lxor = (uint32_t)((l & 7) << 4);
    const uint32_t a_row_off = (uint32_t)((wm + (l & 15)) * ROW_BYTES);
    const uint32_t a_khalf   = (uint32_t)((l >> 4) * 16);
    const uint32_t b_row_off = (uint32_t)((wn + (l & 7)) * ROW_BYTES);
    const int quad = l >> 3;
    const uint32_t b_nt_off  = (uint32_t)(((quad >> 1) * 8) * ROW_BYTES);
    const uint32_t b_khalf   = (uint32_t)((quad & 1) * 16);

    int g = 0;
    for (int t2 = tile0; t2 < NTILES; t2 += GRID) {
        const int bm = (t2 >> 4) * BM;
        const int bn = (t2 & 15) * BN;

        for (int kit = 0; kit < KITERS; kit++, g++) {
            const int s = g & 3;
            const int fl = g >> 2;

            // consumer: wait for global iteration g's stage (fill #fl)
            MBARRIER_WAIT(sbase + OFF_FULL + 8 * s, fl & 1);

            const uint32_t stA = sbase + OFF_TILES + s * STAGE_BYTES;
            const uint32_t stB = stA + A_BYTES;

#pragma unroll
            for (int kk = 0; kk < 4; kk++) {        // k16 steps within BK=64
                uint32_t a[4][4], b[8][2];
#pragma unroll
                for (int mi = 0; mi < 4; mi++) {
                    uint32_t addr = stA + a_row_off + (uint32_t)(mi * 16 * ROW_BYTES)
                                  + (((uint32_t)(kk * 32) + a_khalf) ^ lxor);
                    ldsm_x4(a[mi][0], a[mi][1], a[mi][2], a[mi][3], addr);
                }
#pragma unroll
                for (int nj = 0; nj < 4; nj++) {    // each x4 covers 2 n8 tiles
                    uint32_t addr = stB + b_row_off + (uint32_t)(nj * 16 * ROW_BYTES)
                                  + b_nt_off
                                  + (((uint32_t)(kk * 32) + b_khalf) ^ lxor);
                    ldsm_x4(b[nj * 2][0], b[nj * 2][1],
                            b[nj * 2 + 1][0], b[nj * 2 + 1][1], addr);
                }
                if (kk == 3)      // all smem reads of this stage issued
                    MBARRIER_ARRIVE(sbase + OFF_EMPTY + 8 * s);
#pragma unroll
                for (int mi = 0; mi < 4; mi++)
#pragma unroll
                    for (int ni = 0; ni < 8; ni++)
                        mma16816(acc[mi][ni][0], acc[mi][ni][1],
                                 acc[mi][ni][2], acc[mi][ni][3],
                                 a[mi][0], a[mi][1], a[mi][2], a[mi][3],
                                 b[ni][0], b[ni][1]);
            }

            // producer: fill global iteration g+3 (may belong to the NEXT tile)
            const int gn = g + 3;
            {
                const int lt2 = gn >> 6;
                if (tile0 + lt2 * GRID < NTILES) {
                    const int s2 = gn & 3;
                    const int f2 = gn >> 2;
                    if (gn >= STAGES)   // wait consumers of fill f2-1 (done at g-1)
                        MBARRIER_WAIT(sbase + OFF_EMPTY + 8 * s2, (f2 - 1) & 1);
                    load_iter(tid, sbase, tile0, gn);
                }
            }
        }

        // epilogue for tile (bm, bn): acc regs only, scale/bias via read-only
        // cache — no smem, no barrier; overlaps the next tile's prefetch.
        const int row0 = bm + wm + (l >> 2);
        const int col0 = wn + (l & 3) * 2;
#pragma unroll
        for (int mi = 0; mi < 4; mi++) {
#pragma unroll
            for (int ni = 0; ni < 8; ni++) {
                const int n = bn + col0 + ni * 8;
                const float s0 = __ldg(scale + n),     s1 = __ldg(scale + n + 1);
                const float b0 = __ldg(bias + n),      b1 = __ldg(bias + n + 1);
                float* p0 = out + (size_t)(row0 + mi * 16) * N_TOT + n;
                float* p1 = p0 + 8 * N_TOT;
                float2 v0 = make_float2(fmaf(acc[mi][ni][0], s0, b0),
                                        fmaf(acc[mi][ni][1], s1, b1));
                float2 v1 = make_float2(fmaf(acc[mi][ni][2], s0, b0),
                                        fmaf(acc[mi][ni][3], s1, b1));
                *reinterpret_cast<float2*>(p0) = v0;
                *reinterpret_cast<float2*>(p1) = v1;
                acc[mi][ni][0] = 0.0f; acc[mi][ni][1] = 0.0f;
                acc[mi][ni][2] = 0.0f; acc[mi][ni][3] = 0.0f;
            }
        }
    }
}

// ---------------------------------------------------------------------------
// launch
// ---------------------------------------------------------------------------
extern "C" void kernel_launch(void* const* d_in, const int* in_sizes, int n_in,
                              void* d_out, int out_size) {
    const float* x     = (const float*)d_in[0];
    const int*   w_q   = (const int*)d_in[1];
    const float* scale = (const float*)d_in[2];
    const float* bias  = (const float*)d_in[3];
    float* out = (float*)d_out;

    {
        int total = N4X + N4W;
        convert_all_kernel<<<(total + 255) / 256, 256>>>(x, w_q);
    }
    {
        static bool attr_set = false;
        if (!attr_set) {
            cudaFuncSetAttribute(qgemm_mma_kernel,
                                 cudaFuncAttributeMaxDynamicSharedMemorySize, SMEM_TOTAL);
            attr_set = true;
        }
        qgemm_mma_kernel<<<GRID, NTHREADS, SMEM_TOTAL>>>(scale, bias, out);
    }
}